// round 2
// baseline (speedup 1.0000x reference)
#include <cuda_runtime.h>

#define NN 100000
#define NE 600000
#define C 128
#define OC 64
#define NREL 3
#define PAD 132   // 128 + 4 pad, keeps 16B alignment (132 % 4 == 0)

// ---------------- scratch (static device globals; no allocation allowed) ----
__device__ float g_agg[(size_t)NREL * NN * C];   // per-relation edge sums
__device__ float g_cnt[NREL * NN];               // per-relation in-degree
__device__ float g_h[(size_t)NN * C];            // hidden after relu-mean
__device__ float g_t[(size_t)NN * OC];           // h @ Wl_f (pre-aggregation)
__device__ float g_aggF[(size_t)NN * OC];        // final-layer edge sums of t
__device__ float g_po[(size_t)NN * OC];          // h @ Wr_f + b_f

__device__ __forceinline__ void red_add_v4(float* p, float4 v) {
    asm volatile("red.global.add.v4.f32 [%0], {%1, %2, %3, %4};"
                 :: "l"(p), "f"(v.x), "f"(v.y), "f"(v.z), "f"(v.w)
                 : "memory");
}

// ---------------- kernel 0: zero accumulators -------------------------------
__global__ void k_zero() {
    size_t i = (size_t)blockIdx.x * blockDim.x + threadIdx.x;
    size_t stride = (size_t)gridDim.x * blockDim.x;
    float4* a4 = reinterpret_cast<float4*>(g_agg);
    size_t na4 = (size_t)NREL * NN * C / 4;
    for (size_t j = i; j < na4; j += stride) a4[j] = make_float4(0.f, 0.f, 0.f, 0.f);
    for (size_t j = i; j < (size_t)NREL * NN; j += stride) g_cnt[j] = 0.f;
    float4* f4 = reinterpret_cast<float4*>(g_aggF);
    size_t nf4 = (size_t)NN * OC / 4;
    for (size_t j = i; j < nf4; j += stride) f4[j] = make_float4(0.f, 0.f, 0.f, 0.f);
}

// ---------------- kernel 1: scatter x[src] into agg[dst] (one warp / edge) --
// NOTE: edge indices are int32 (JAX silently downgrades int64 without x64 mode).
__global__ void k_scatter_x(const float* __restrict__ x,
                            const int* __restrict__ ei, int r) {
    int w = (blockIdx.x * blockDim.x + threadIdx.x) >> 5;
    int lane = threadIdx.x & 31;
    if (w >= NE) return;
    int src = ei[w];
    int dst = ei[NE + w];
    if ((unsigned)src >= NN || (unsigned)dst >= NN) return;  // defensive
    float4 v = *reinterpret_cast<const float4*>(x + (size_t)src * C + lane * 4);
    float* a = g_agg + (size_t)r * NN * C + (size_t)dst * C + lane * 4;
    red_add_v4(a, v);
    if (lane == 0) atomicAdd(&g_cnt[r * NN + dst], 1.f);
}

// ---------------- kernel 2: fused 3-relation SAGE GEMM ----------------------
// h[n] = (1/3) * sum_r relu( mean_agg_r[n] @ Wl[r] + bl[r] + x[n] @ Wr[r] )
// Tile: 128 nodes x 128 cols, 256 threads, each thread 8x8 micro-tile.
__global__ __launch_bounds__(256, 1)
void k_gemm1(const float* __restrict__ x, const float* __restrict__ Wl,
             const float* __restrict__ bl, const float* __restrict__ Wr) {
    extern __shared__ float sm[];
    float* X_s  = sm;                  // [128][PAD] x tile
    float* A_s  = X_s + 128 * PAD;     // [128][PAD] mean-agg tile
    float* Wl_s = A_s + 128 * PAD;     // [32][PAD]  Wl k-chunk
    float* Wr_s = Wl_s + 32 * PAD;     // [32][PAD]  Wr k-chunk

    int tid = threadIdx.x;
    int node0 = blockIdx.x * 128;
    int ty = tid >> 4;   // 0..15 -> node group
    int tx = tid & 15;   // 0..15 -> col group

    // stage x tile (zero-pad past NN)
    for (int idx = tid; idx < 128 * 32; idx += 256) {
        int row = idx >> 5, c4 = idx & 31;
        int node = node0 + row;
        float4 v = make_float4(0.f, 0.f, 0.f, 0.f);
        if (node < NN)
            v = *reinterpret_cast<const float4*>(x + (size_t)node * C + c4 * 4);
        float* d = X_s + row * PAD + c4 * 4;
        d[0] = v.x; d[1] = v.y; d[2] = v.z; d[3] = v.w;
    }

    float accH[8][8];
#pragma unroll
    for (int i = 0; i < 8; i++)
#pragma unroll
        for (int j = 0; j < 8; j++) accH[i][j] = 0.f;

    for (int r = 0; r < NREL; r++) {
        __syncthreads();  // protect A_s from previous iteration's readers
        // stage mean-agg tile for relation r
        for (int idx = tid; idx < 128 * 32; idx += 256) {
            int row = idx >> 5, c4 = idx & 31;
            int node = node0 + row;
            float4 v = make_float4(0.f, 0.f, 0.f, 0.f);
            if (node < NN) {
                float inv = 1.f / fmaxf(g_cnt[r * NN + node], 1.f);
                const float* ap =
                    g_agg + (size_t)r * NN * C + (size_t)node * C + c4 * 4;
                v.x = ap[0] * inv; v.y = ap[1] * inv;
                v.z = ap[2] * inv; v.w = ap[3] * inv;
            }
            float* d = A_s + row * PAD + c4 * 4;
            d[0] = v.x; d[1] = v.y; d[2] = v.z; d[3] = v.w;
        }

        float accX[8][8];
#pragma unroll
        for (int j = 0; j < 8; j++) {
            float b = bl[r * C + tx * 8 + j];
#pragma unroll
            for (int i = 0; i < 8; i++) accX[i][j] = b;
        }

        for (int kc = 0; kc < 4; kc++) {
            __syncthreads();
            // stage 32-row k-chunk of Wl[r], Wr[r]
            for (int idx = tid; idx < 32 * 32; idx += 256) {
                int kk = idx >> 5, c4 = idx & 31;
                size_t off = (size_t)r * C * C + (size_t)(kc * 32 + kk) * C + c4 * 4;
                float4 vl = *reinterpret_cast<const float4*>(Wl + off);
                float4 vr = *reinterpret_cast<const float4*>(Wr + off);
                float* dl = Wl_s + kk * PAD + c4 * 4;
                dl[0] = vl.x; dl[1] = vl.y; dl[2] = vl.z; dl[3] = vl.w;
                float* dr = Wr_s + kk * PAD + c4 * 4;
                dr[0] = vr.x; dr[1] = vr.y; dr[2] = vr.z; dr[3] = vr.w;
            }
            __syncthreads();

#pragma unroll 8
            for (int kk = 0; kk < 32; kk++) {
                int k = kc * 32 + kk;
                float af[8], xf[8];
#pragma unroll
                for (int i = 0; i < 8; i++) {
                    af[i] = A_s[(ty * 8 + i) * PAD + k];
                    xf[i] = X_s[(ty * 8 + i) * PAD + k];
                }
                float4 wl0 = *reinterpret_cast<const float4*>(Wl_s + kk * PAD + tx * 8);
                float4 wl1 = *reinterpret_cast<const float4*>(Wl_s + kk * PAD + tx * 8 + 4);
                float4 wr0 = *reinterpret_cast<const float4*>(Wr_s + kk * PAD + tx * 8);
                float4 wr1 = *reinterpret_cast<const float4*>(Wr_s + kk * PAD + tx * 8 + 4);
                float wlv[8] = {wl0.x, wl0.y, wl0.z, wl0.w, wl1.x, wl1.y, wl1.z, wl1.w};
                float wrv[8] = {wr0.x, wr0.y, wr0.z, wr0.w, wr1.x, wr1.y, wr1.z, wr1.w};
#pragma unroll
                for (int i = 0; i < 8; i++)
#pragma unroll
                    for (int j = 0; j < 8; j++)
                        accX[i][j] += af[i] * wlv[j] + xf[i] * wrv[j];
            }
        }

#pragma unroll
        for (int i = 0; i < 8; i++)
#pragma unroll
            for (int j = 0; j < 8; j++)
                accH[i][j] += fmaxf(accX[i][j], 0.f) * (1.f / 3.f);
    }

    // write h
#pragma unroll
    for (int i = 0; i < 8; i++) {
        int node = node0 + ty * 8 + i;
        if (node < NN) {
            float* hp = g_h + (size_t)node * C + tx * 8;
            *reinterpret_cast<float4*>(hp) =
                make_float4(accH[i][0], accH[i][1], accH[i][2], accH[i][3]);
            *reinterpret_cast<float4*>(hp + 4) =
                make_float4(accH[i][4], accH[i][5], accH[i][6], accH[i][7]);
        }
    }
}

// ---------------- kernel 3: t = h @ Wl_f ; po = h @ Wr_f + b_f --------------
// Tile: 128 nodes x 64 cols, 256 threads, each thread 4x8 micro-tile (x2 outputs).
#define WPAD 68
__global__ __launch_bounds__(256, 1)
void k_gemm2(const float* __restrict__ Wlf, const float* __restrict__ blf,
             const float* __restrict__ Wrf) {
    extern __shared__ float sm[];
    float* H_s  = sm;                   // [128][PAD]
    float* Wl_s = H_s + 128 * PAD;      // [128][WPAD]
    float* Wr_s = Wl_s + 128 * WPAD;    // [128][WPAD]

    int tid = threadIdx.x;
    int node0 = blockIdx.x * 128;
    int ty = tid >> 3;  // 0..31 -> 4 nodes each
    int tx = tid & 7;   // 0..7  -> 8 cols each

    for (int idx = tid; idx < 128 * 32; idx += 256) {
        int row = idx >> 5, c4 = idx & 31;
        int node = node0 + row;
        float4 v = make_float4(0.f, 0.f, 0.f, 0.f);
        if (node < NN)
            v = *reinterpret_cast<const float4*>(g_h + (size_t)node * C + c4 * 4);
        float* d = H_s + row * PAD + c4 * 4;
        d[0] = v.x; d[1] = v.y; d[2] = v.z; d[3] = v.w;
    }
    for (int idx = tid; idx < 128 * 16; idx += 256) {
        int k = idx >> 4, c4 = idx & 15;
        float4 vl = *reinterpret_cast<const float4*>(Wlf + (size_t)k * OC + c4 * 4);
        float4 vr = *reinterpret_cast<const float4*>(Wrf + (size_t)k * OC + c4 * 4);
        float* dl = Wl_s + k * WPAD + c4 * 4;
        dl[0] = vl.x; dl[1] = vl.y; dl[2] = vl.z; dl[3] = vl.w;
        float* dr = Wr_s + k * WPAD + c4 * 4;
        dr[0] = vr.x; dr[1] = vr.y; dr[2] = vr.z; dr[3] = vr.w;
    }
    __syncthreads();

    float at[4][8], ap[4][8];
#pragma unroll
    for (int j = 0; j < 8; j++) {
        float b = blf[tx * 8 + j];
#pragma unroll
        for (int i = 0; i < 4; i++) { at[i][j] = 0.f; ap[i][j] = b; }
    }

#pragma unroll 8
    for (int k = 0; k < C; k++) {
        float hv[4];
#pragma unroll
        for (int i = 0; i < 4; i++) hv[i] = H_s[(ty * 4 + i) * PAD + k];
        float4 wl0 = *reinterpret_cast<const float4*>(Wl_s + k * WPAD + tx * 8);
        float4 wl1 = *reinterpret_cast<const float4*>(Wl_s + k * WPAD + tx * 8 + 4);
        float4 wr0 = *reinterpret_cast<const float4*>(Wr_s + k * WPAD + tx * 8);
        float4 wr1 = *reinterpret_cast<const float4*>(Wr_s + k * WPAD + tx * 8 + 4);
        float wlv[8] = {wl0.x, wl0.y, wl0.z, wl0.w, wl1.x, wl1.y, wl1.z, wl1.w};
        float wrv[8] = {wr0.x, wr0.y, wr0.z, wr0.w, wr1.x, wr1.y, wr1.z, wr1.w};
#pragma unroll
        for (int i = 0; i < 4; i++)
#pragma unroll
            for (int j = 0; j < 8; j++) {
                at[i][j] += hv[i] * wlv[j];
                ap[i][j] += hv[i] * wrv[j];
            }
    }

#pragma unroll
    for (int i = 0; i < 4; i++) {
        int node = node0 + ty * 4 + i;
        if (node < NN) {
            float* tp = g_t + (size_t)node * OC + tx * 8;
            *reinterpret_cast<float4*>(tp) =
                make_float4(at[i][0], at[i][1], at[i][2], at[i][3]);
            *reinterpret_cast<float4*>(tp + 4) =
                make_float4(at[i][4], at[i][5], at[i][6], at[i][7]);
            float* pp = g_po + (size_t)node * OC + tx * 8;
            *reinterpret_cast<float4*>(pp) =
                make_float4(ap[i][0], ap[i][1], ap[i][2], ap[i][3]);
            *reinterpret_cast<float4*>(pp + 4) =
                make_float4(ap[i][4], ap[i][5], ap[i][6], ap[i][7]);
        }
    }
}

// ---------------- kernel 4: scatter t[src] into aggF[dst] (ei0) -------------
// Half-warp per edge: 16 lanes x 16B = 256B row (v4 reductions).
__global__ void k_scatter_t(const int* __restrict__ ei) {
    int hw = (blockIdx.x * blockDim.x + threadIdx.x) >> 4;  // half-warp id
    int lane = threadIdx.x & 15;
    if (hw >= NE) return;
    int src = ei[hw];
    int dst = ei[NE + hw];
    if ((unsigned)src >= NN || (unsigned)dst >= NN) return;  // defensive
    float4 v = *reinterpret_cast<const float4*>(g_t + (size_t)src * OC + lane * 4);
    red_add_v4(g_aggF + (size_t)dst * OC + lane * 4, v);
}

// ---------------- kernel 5: out = aggF / max(cnt0,1) + po -------------------
__global__ void k_final(float* __restrict__ out) {
    int i = blockIdx.x * blockDim.x + threadIdx.x;
    int stride = gridDim.x * blockDim.x;
    int n4 = NN * OC / 4;
    const float4* a4 = reinterpret_cast<const float4*>(g_aggF);
    const float4* p4 = reinterpret_cast<const float4*>(g_po);
    float4* o4 = reinterpret_cast<float4*>(out);
    for (int j = i; j < n4; j += stride) {
        int node = j / (OC / 4);
        float inv = 1.f / fmaxf(g_cnt[node], 1.f);  // relation-0 counts
        float4 a = a4[j];
        float4 p = p4[j];
        o4[j] = make_float4(a.x * inv + p.x, a.y * inv + p.y,
                            a.z * inv + p.z, a.w * inv + p.w);
    }
}

// ---------------- launch ----------------------------------------------------
extern "C" void kernel_launch(void* const* d_in, const int* in_sizes, int n_in,
                              void* d_out, int out_size) {
    const float* x   = (const float*)d_in[0];
    const float* Wl  = (const float*)d_in[1];
    const float* bl  = (const float*)d_in[2];
    const float* Wr  = (const float*)d_in[3];
    const float* Wlf = (const float*)d_in[4];
    const float* blf = (const float*)d_in[5];
    const float* Wrf = (const float*)d_in[6];
    const int* ei0   = (const int*)d_in[7];
    const int* ei1   = (const int*)d_in[8];
    const int* ei2   = (const int*)d_in[9];
    float* out = (float*)d_out;

    const int SMEM1 = (128 * PAD * 2 + 32 * PAD * 2) * (int)sizeof(float);   // 168960
    const int SMEM2 = (128 * PAD + 2 * 128 * WPAD) * (int)sizeof(float);     // 137216
    cudaFuncSetAttribute(k_gemm1, cudaFuncAttributeMaxDynamicSharedMemorySize, SMEM1);
    cudaFuncSetAttribute(k_gemm2, cudaFuncAttributeMaxDynamicSharedMemorySize, SMEM2);

    k_zero<<<2048, 256>>>();

    int sb = (NE * 32 + 255) / 256;  // warp per edge
    k_scatter_x<<<sb, 256>>>(x, ei0, 0);
    k_scatter_x<<<sb, 256>>>(x, ei1, 1);
    k_scatter_x<<<sb, 256>>>(x, ei2, 2);

    int gb = (NN + 127) / 128;  // 782
    k_gemm1<<<gb, 256, SMEM1>>>(x, Wl, bl, Wr);
    k_gemm2<<<gb, 256, SMEM2>>>(Wlf, blf, Wrf);

    int sb2 = (NE * 16 + 255) / 256;  // half-warp per edge
    k_scatter_t<<<sb2, 256>>>(ei0);
    k_final<<<2048, 256>>>(out);
}

// round 4
// speedup vs baseline: 1.3615x; 1.3615x over previous
#include <cuda_runtime.h>
#include <mma.h>
#include <cstdint>

using namespace nvcuda;

#define NN 100000
#define NE 600000
#define C 128
#define OC 64
#define NREL 3
#define LDS_ 132   // smem row stride in floats

// ---------------- scratch (static device globals) ---------------------------
__device__ float g_agg[(size_t)NREL * NN * C];   // per-relation edge sums
__device__ float g_cnt[NREL * NN];               // per-relation in-degree
__device__ float g_t[(size_t)NN * OC];           // h @ Wl_f (pre-aggregation)
__device__ float g_aggF[(size_t)NN * OC];        // final-layer edge sums of t
__device__ float g_po[(size_t)NN * OC];          // h @ Wr_f + b_f

__device__ __forceinline__ float f2tf32f(float f) {
    uint32_t u;
    asm("cvt.rna.tf32.f32 %0, %1;" : "=r"(u) : "f"(f));
    return __uint_as_float(u);
}
__device__ __forceinline__ void red_add_v4(float* p, float4 v) {
    asm volatile("red.global.add.v4.f32 [%0], {%1, %2, %3, %4};"
                 :: "l"(p), "f"(v.x), "f"(v.y), "f"(v.z), "f"(v.w) : "memory");
}

// ---------------- kernel 0: zero accumulators -------------------------------
__global__ void k_zero() {
    size_t i = (size_t)blockIdx.x * blockDim.x + threadIdx.x;
    size_t stride = (size_t)gridDim.x * blockDim.x;
    float4* a4 = reinterpret_cast<float4*>(g_agg);
    size_t na4 = (size_t)NREL * NN * C / 4;
    for (size_t j = i; j < na4; j += stride) a4[j] = make_float4(0.f, 0.f, 0.f, 0.f);
    for (size_t j = i; j < (size_t)NREL * NN; j += stride) g_cnt[j] = 0.f;
    float4* f4 = reinterpret_cast<float4*>(g_aggF);
    size_t nf4 = (size_t)NN * OC / 4;
    for (size_t j = i; j < nf4; j += stride) f4[j] = make_float4(0.f, 0.f, 0.f, 0.f);
}

// ---------------- kernel 1: scatter x[src] into agg[dst] --------------------
__global__ void k_scatter_x(const float* __restrict__ x,
                            const int* __restrict__ ei, int r) {
    int w = (blockIdx.x * blockDim.x + threadIdx.x) >> 5;
    int lane = threadIdx.x & 31;
    if (w >= NE) return;
    int src = ei[w];
    int dst = ei[NE + w];
    if ((unsigned)src >= NN || (unsigned)dst >= NN) return;
    float4 v = *reinterpret_cast<const float4*>(x + (size_t)src * C + lane * 4);
    red_add_v4(g_agg + (size_t)r * NN * C + (size_t)dst * C + lane * 4, v);
    if (lane == 0) atomicAdd(&g_cnt[r * NN + dst], 1.f);
}

// ---------------- fused tf32 WMMA GEMM kernel -------------------------------
// Per 128-node tile (256 threads, 8 warps in 2x4, warp tile 64x32):
//   D_r = mean_agg_r @ Wl_r + x @ Wr_r
//   h  += relu(D_r + bl_r)/3        (register accumulation via smem roundtrip)
//   D_f = h @ [Wlf | Wrf]
//   g_t = D_f[:,0:64] ; g_po = D_f[:,64:128] + blf
__global__ __launch_bounds__(256, 1)
void k_gemm_fused(const float* __restrict__ x,  const float* __restrict__ Wl,
                  const float* __restrict__ bl, const float* __restrict__ Wr,
                  const float* __restrict__ Wlf, const float* __restrict__ blf,
                  const float* __restrict__ Wrf) {
    extern __shared__ float sm[];
    float* bls  = sm;                       // 384 floats
    float* blfs = sm + 384;                 // 64 floats
    float* X_s  = sm + 512;                 // [128][LDS_]
    float* A_s  = X_s + 128 * LDS_;         // [128][LDS_] (agg / D / h scratch)
    float* Wl_s = A_s + 128 * LDS_;         // [64][LDS_]
    float* Wr_s = Wl_s + 64 * LDS_;         // [64][LDS_]

    int tid  = threadIdx.x;
    int wid  = tid >> 5;
    int node0 = blockIdx.x * 128;
    int wm = (wid >> 2) * 64;   // warp row offset
    int wn = (wid & 3) * 32;    // warp col offset

    // epilogue ownership: thread owns row = tid>>1, cols c0..c0+63
    int erow = tid >> 1;
    int ec0  = (tid & 1) * 64;

    // stage biases
    for (int i = tid; i < NREL * C; i += 256) bls[i] = bl[i];
    if (tid < OC) blfs[tid] = blf[tid];

    // stage X tile (tf32-rounded)
    for (int it = tid; it < 128 * 32; it += 256) {
        int row = it >> 5, c4 = it & 31;
        int node = node0 + row;
        float4 v = make_float4(0.f, 0.f, 0.f, 0.f);
        if (node < NN)
            v = *reinterpret_cast<const float4*>(x + (size_t)node * C + c4 * 4);
        float* d = X_s + row * LDS_ + c4 * 4;
        d[0] = f2tf32f(v.x); d[1] = f2tf32f(v.y);
        d[2] = f2tf32f(v.z); d[3] = f2tf32f(v.w);
    }

    float hreg[64];
#pragma unroll
    for (int j = 0; j < 64; j++) hreg[j] = 0.f;
    const float inv3 = 1.f / 3.f;

    for (int r = 0; r < NREL; r++) {
        __syncthreads();  // A_s free (prior epilogue / X stage done)
        // stage mean-agg tile for relation r (tf32-rounded)
        {
            const float* aggr = g_agg + (size_t)r * NN * C;
            const float* cntr = g_cnt + r * NN;
            for (int it = tid; it < 128 * 32; it += 256) {
                int row = it >> 5, c4 = it & 31;
                int node = node0 + row;
                float4 v = make_float4(0.f, 0.f, 0.f, 0.f);
                if (node < NN) {
                    float inv = 1.f / fmaxf(cntr[node], 1.f);
                    float4 a = *reinterpret_cast<const float4*>(
                        aggr + (size_t)node * C + c4 * 4);
                    v.x = a.x * inv; v.y = a.y * inv;
                    v.z = a.z * inv; v.w = a.w * inv;
                }
                float* d = A_s + row * LDS_ + c4 * 4;
                d[0] = f2tf32f(v.x); d[1] = f2tf32f(v.y);
                d[2] = f2tf32f(v.z); d[3] = f2tf32f(v.w);
            }
        }

        wmma::fragment<wmma::accumulator, 16, 16, 8, float> acc[4][2];
#pragma unroll
        for (int i = 0; i < 4; i++)
#pragma unroll
            for (int j = 0; j < 2; j++) wmma::fill_fragment(acc[i][j], 0.f);

        for (int kh = 0; kh < 2; kh++) {
            __syncthreads();  // prior W consumers done / A_s staged
            // stage k-half of Wl[r], Wr[r]: rows kk (local k), cols n
            for (int it = tid; it < 64 * 32; it += 256) {
                int kk = it >> 5, c4 = it & 31;
                size_t off = (size_t)r * C * C + (size_t)(kh * 64 + kk) * C + c4 * 4;
                float4 vl = *reinterpret_cast<const float4*>(Wl + off);
                float4 vr = *reinterpret_cast<const float4*>(Wr + off);
                float* dl = Wl_s + kk * LDS_ + c4 * 4;
                dl[0] = f2tf32f(vl.x); dl[1] = f2tf32f(vl.y);
                dl[2] = f2tf32f(vl.z); dl[3] = f2tf32f(vl.w);
                float* dr = Wr_s + kk * LDS_ + c4 * 4;
                dr[0] = f2tf32f(vr.x); dr[1] = f2tf32f(vr.y);
                dr[2] = f2tf32f(vr.z); dr[3] = f2tf32f(vr.w);
            }
            __syncthreads();

#pragma unroll
            for (int ks = 0; ks < 8; ks++) {
                int kloc = ks * 8;              // W row (local)
                int kglb = kh * 64 + kloc;      // A/X col
                wmma::fragment<wmma::matrix_a, 16, 16, 8, wmma::precision::tf32,
                               wmma::row_major> af[4], xf[4];
                wmma::fragment<wmma::matrix_b, 16, 16, 8, wmma::precision::tf32,
                               wmma::row_major> lf[2], rf[2];
#pragma unroll
                for (int i = 0; i < 4; i++) {
                    wmma::load_matrix_sync(af[i], A_s + (wm + i * 16) * LDS_ + kglb, LDS_);
                    wmma::load_matrix_sync(xf[i], X_s + (wm + i * 16) * LDS_ + kglb, LDS_);
                }
#pragma unroll
                for (int j = 0; j < 2; j++) {
                    wmma::load_matrix_sync(lf[j], Wl_s + kloc * LDS_ + wn + j * 16, LDS_);
                    wmma::load_matrix_sync(rf[j], Wr_s + kloc * LDS_ + wn + j * 16, LDS_);
                }
#pragma unroll
                for (int i = 0; i < 4; i++)
#pragma unroll
                    for (int j = 0; j < 2; j++) {
                        wmma::mma_sync(acc[i][j], af[i], lf[j], acc[i][j]);
                        wmma::mma_sync(acc[i][j], xf[i], rf[j], acc[i][j]);
                    }
            }
        }

        __syncthreads();  // all warps done reading A_s
        // dump D_r fragments into A_s
#pragma unroll
        for (int i = 0; i < 4; i++)
#pragma unroll
            for (int j = 0; j < 2; j++)
                wmma::store_matrix_sync(A_s + (wm + i * 16) * LDS_ + wn + j * 16,
                                        acc[i][j], LDS_, wmma::mem_row_major);
        __syncthreads();

        // epilogue: h += relu(D + bias)/3
#pragma unroll
        for (int q = 0; q < 16; q++) {
            int c = ec0 + q * 4;
            float4 d = *reinterpret_cast<const float4*>(A_s + erow * LDS_ + c);
            float4 b = *reinterpret_cast<const float4*>(bls + r * C + c);
            hreg[q * 4 + 0] += fmaxf(d.x + b.x, 0.f) * inv3;
            hreg[q * 4 + 1] += fmaxf(d.y + b.y, 0.f) * inv3;
            hreg[q * 4 + 2] += fmaxf(d.z + b.z, 0.f) * inv3;
            hreg[q * 4 + 3] += fmaxf(d.w + b.w, 0.f) * inv3;
        }
    }

    // ---------------- second GEMM: D_f = h @ [Wlf | Wrf] --------------------
    __syncthreads();  // everyone finished epilogue reads of A_s
    // write h (tf32-rounded) into A_s
#pragma unroll
    for (int q = 0; q < 16; q++) {
        int c = ec0 + q * 4;
        float4 v;
        v.x = f2tf32f(hreg[q * 4 + 0]); v.y = f2tf32f(hreg[q * 4 + 1]);
        v.z = f2tf32f(hreg[q * 4 + 2]); v.w = f2tf32f(hreg[q * 4 + 3]);
        *reinterpret_cast<float4*>(A_s + erow * LDS_ + c) = v;
    }
    // stage Wf = [Wlf | Wrf] : k rows 0..63 -> Wl_s, 64..127 -> Wr_s
    for (int it = tid; it < 128 * 32; it += 256) {
        int k = it >> 5, c4 = it & 31;
        int col = c4 * 4;
        float4 v;
        if (col < OC)
            v = *reinterpret_cast<const float4*>(Wlf + (size_t)k * OC + col);
        else
            v = *reinterpret_cast<const float4*>(Wrf + (size_t)k * OC + (col - OC));
        float* d = ((k < 64) ? Wl_s + k * LDS_ : Wr_s + (k - 64) * LDS_) + col;
        d[0] = f2tf32f(v.x); d[1] = f2tf32f(v.y);
        d[2] = f2tf32f(v.z); d[3] = f2tf32f(v.w);
    }
    __syncthreads();

    {
        wmma::fragment<wmma::accumulator, 16, 16, 8, float> acc2[4][2];
#pragma unroll
        for (int i = 0; i < 4; i++)
#pragma unroll
            for (int j = 0; j < 2; j++) wmma::fill_fragment(acc2[i][j], 0.f);

#pragma unroll
        for (int ks = 0; ks < 16; ks++) {
            int k = ks * 8;
            const float* wbase = (k < 64) ? (Wl_s + k * LDS_)
                                          : (Wr_s + (k - 64) * LDS_);
            wmma::fragment<wmma::matrix_a, 16, 16, 8, wmma::precision::tf32,
                           wmma::row_major> hf[4];
            wmma::fragment<wmma::matrix_b, 16, 16, 8, wmma::precision::tf32,
                           wmma::row_major> wf[2];
#pragma unroll
            for (int i = 0; i < 4; i++)
                wmma::load_matrix_sync(hf[i], A_s + (wm + i * 16) * LDS_ + k, LDS_);
#pragma unroll
            for (int j = 0; j < 2; j++)
                wmma::load_matrix_sync(wf[j], wbase + wn + j * 16, LDS_);
#pragma unroll
            for (int i = 0; i < 4; i++)
#pragma unroll
                for (int j = 0; j < 2; j++)
                    wmma::mma_sync(acc2[i][j], hf[i], wf[j], acc2[i][j]);
        }

        __syncthreads();  // all warps done reading h from A_s
#pragma unroll
        for (int i = 0; i < 4; i++)
#pragma unroll
            for (int j = 0; j < 2; j++)
                wmma::store_matrix_sync(A_s + (wm + i * 16) * LDS_ + wn + j * 16,
                                        acc2[i][j], LDS_, wmma::mem_row_major);
        __syncthreads();
    }

    // epilogue 2: t / po
    {
        int node = node0 + erow;
        if (node < NN) {
            if (ec0 == 0) {
                float* tp = g_t + (size_t)node * OC;
#pragma unroll
                for (int q = 0; q < 16; q++)
                    *reinterpret_cast<float4*>(tp + q * 4) =
                        *reinterpret_cast<const float4*>(A_s + erow * LDS_ + q * 4);
            } else {
                float* pp = g_po + (size_t)node * OC;
#pragma unroll
                for (int q = 0; q < 16; q++) {
                    float4 d = *reinterpret_cast<const float4*>(
                        A_s + erow * LDS_ + 64 + q * 4);
                    float4 b = *reinterpret_cast<const float4*>(blfs + q * 4);
                    *reinterpret_cast<float4*>(pp + q * 4) = make_float4(
                        d.x + b.x, d.y + b.y, d.z + b.z, d.w + b.w);
                }
            }
        }
    }
}

// ---------------- kernel 4: scatter t[src] into aggF[dst] (ei0) -------------
__global__ void k_scatter_t(const int* __restrict__ ei) {
    int hw = (blockIdx.x * blockDim.x + threadIdx.x) >> 4;
    int lane = threadIdx.x & 15;
    if (hw >= NE) return;
    int src = ei[hw];
    int dst = ei[NE + hw];
    if ((unsigned)src >= NN || (unsigned)dst >= NN) return;
    float4 v = *reinterpret_cast<const float4*>(g_t + (size_t)src * OC + lane * 4);
    red_add_v4(g_aggF + (size_t)dst * OC + lane * 4, v);
}

// ---------------- kernel 5: out = aggF / max(cnt0,1) + po -------------------
__global__ void k_final(float* __restrict__ out) {
    int i = blockIdx.x * blockDim.x + threadIdx.x;
    int stride = gridDim.x * blockDim.x;
    int n4 = NN * OC / 4;
    const float4* a4 = reinterpret_cast<const float4*>(g_aggF);
    const float4* p4 = reinterpret_cast<const float4*>(g_po);
    float4* o4 = reinterpret_cast<float4*>(out);
    for (int j = i; j < n4; j += stride) {
        int node = j / (OC / 4);
        float inv = 1.f / fmaxf(g_cnt[node], 1.f);
        float4 a = a4[j];
        float4 p = p4[j];
        o4[j] = make_float4(a.x * inv + p.x, a.y * inv + p.y,
                            a.z * inv + p.z, a.w * inv + p.w);
    }
}

// ---------------- launch ----------------------------------------------------
extern "C" void kernel_launch(void* const* d_in, const int* in_sizes, int n_in,
                              void* d_out, int out_size) {
    const float* x   = (const float*)d_in[0];
    const float* Wl  = (const float*)d_in[1];
    const float* bl  = (const float*)d_in[2];
    const float* Wr  = (const float*)d_in[3];
    const float* Wlf = (const float*)d_in[4];
    const float* blf = (const float*)d_in[5];
    const float* Wrf = (const float*)d_in[6];
    const int* ei0   = (const int*)d_in[7];
    const int* ei1   = (const int*)d_in[8];
    const int* ei2   = (const int*)d_in[9];
    float* out = (float*)d_out;

    const int SMEMF = (512 + 2 * 128 * LDS_ + 2 * 64 * LDS_) * (int)sizeof(float);
    cudaFuncSetAttribute(k_gemm_fused, cudaFuncAttributeMaxDynamicSharedMemorySize, SMEMF);

    k_zero<<<2048, 256>>>();

    int sb = (NE * 32 + 255) / 256;
    k_scatter_x<<<sb, 256>>>(x, ei0, 0);
    k_scatter_x<<<sb, 256>>>(x, ei1, 1);
    k_scatter_x<<<sb, 256>>>(x, ei2, 2);

    int gb = (NN + 127) / 128;  // 782
    k_gemm_fused<<<gb, 256, SMEMF>>>(x, Wl, bl, Wr, Wlf, blf, Wrf);

    int sb2 = (NE * 16 + 255) / 256;
    k_scatter_t<<<sb2, 256>>>(ei0);
    k_final<<<2048, 256>>>(out);
}

// round 5
// speedup vs baseline: 1.8696x; 1.3732x over previous
#include <cuda_runtime.h>
#include <cuda_fp16.h>
#include <mma.h>
#include <cstdint>

using namespace nvcuda;

#define NN 100000
#define NE 600000
#define C 128
#define OC 64
#define NREL 3
#define HLD 136   // half stride for fp16 tiles (mult of 8, 272B rows)
#define FLD 132   // float stride for f32 D scratch

// ---------------- scratch (static device globals) ---------------------------
__device__ float g_agg[(size_t)NREL * NN * C];   // per-relation edge sums
__device__ float g_cnt[NREL * NN];               // per-relation in-degree
__device__ float g_t[(size_t)NN * OC];           // h @ Wl_f (pre-aggregation)
__device__ float g_aggF[(size_t)NN * OC];        // final-layer edge sums of t
__device__ float g_po[(size_t)NN * OC];          // h @ Wr_f + b_f

__device__ __forceinline__ void red_add_v4(float* p, float4 v) {
    asm volatile("red.global.add.v4.f32 [%0], {%1, %2, %3, %4};"
                 :: "l"(p), "f"(v.x), "f"(v.y), "f"(v.z), "f"(v.w) : "memory");
}

// ---------------- kernel 1: scatter x[src] into agg[dst], all 3 relations ---
__global__ void k_scatter_x(const float* __restrict__ x,
                            const int* __restrict__ ei0,
                            const int* __restrict__ ei1,
                            const int* __restrict__ ei2) {
    int r = blockIdx.y;
    const int* ei = (r == 0) ? ei0 : (r == 1) ? ei1 : ei2;
    int w = (blockIdx.x * blockDim.x + threadIdx.x) >> 5;
    int lane = threadIdx.x & 31;
    if (w >= NE) return;
    int src = ei[w];
    int dst = ei[NE + w];
    if ((unsigned)src >= NN || (unsigned)dst >= NN) return;
    float4 v = *reinterpret_cast<const float4*>(x + (size_t)src * C + lane * 4);
    red_add_v4(g_agg + (size_t)r * NN * C + (size_t)dst * C + lane * 4, v);
    if (lane == 0) atomicAdd(&g_cnt[r * NN + dst], 1.f);
}

// ---------------- fused fp16 WMMA GEMM kernel -------------------------------
// Per 128-node tile (256 threads, 8 warps in 2x4, warp tile 64x32):
//   D_r = mean_agg_r @ Wl_r + x @ Wr_r        (fp16 in, fp32 accum)
//   h  += relu(D_r + bl_r)/3
//   D_f = h @ [Wlf | Wrf]
//   g_t = D_f[:,0:64] ; g_po = D_f[:,64:128] + blf
__global__ __launch_bounds__(256, 1)
void k_gemm_fused(const float* __restrict__ x,  const float* __restrict__ Wl,
                  const float* __restrict__ bl, const float* __restrict__ Wr,
                  const float* __restrict__ Wlf, const float* __restrict__ blf,
                  const float* __restrict__ Wrf) {
    extern __shared__ char smraw[];
    float*  bls  = reinterpret_cast<float*>(smraw);            // 384
    float*  blfs = bls + 384;                                  // 64
    __half* X_s  = reinterpret_cast<__half*>(smraw + 2048);    // [128][HLD]
    __half* A_s  = X_s + 128 * HLD;                            // [128][HLD]
    __half* Wl_s = A_s + 128 * HLD;                            // [64][HLD]
    __half* Wr_s = Wl_s + 64 * HLD;                            // [64][HLD]
    float*  D_s  = reinterpret_cast<float*>(
                       smraw + 2048 + (2 * 128 + 2 * 64) * HLD * 2);  // [128][FLD]

    int tid  = threadIdx.x;
    int wid  = tid >> 5;
    int node0 = blockIdx.x * 128;
    int wm = (wid >> 2) * 64;   // warp row offset
    int wn = (wid & 3) * 32;    // warp col offset
    int erow = tid >> 1;        // epilogue row
    int ec0  = (tid & 1) * 64;  // epilogue col base

    // stage biases
    for (int i = tid; i < NREL * C; i += 256) bls[i] = bl[i];
    if (tid < OC) blfs[tid] = blf[tid];

    // stage X tile (fp16)
    for (int it = tid; it < 128 * 32; it += 256) {
        int row = it >> 5, c4 = it & 31;
        int node = node0 + row;
        float4 v = make_float4(0.f, 0.f, 0.f, 0.f);
        if (node < NN)
            v = *reinterpret_cast<const float4*>(x + (size_t)node * C + c4 * 4);
        __half2* d = reinterpret_cast<__half2*>(X_s + row * HLD + c4 * 4);
        d[0] = __floats2half2_rn(v.x, v.y);
        d[1] = __floats2half2_rn(v.z, v.w);
    }

    float hreg[64];
#pragma unroll
    for (int j = 0; j < 64; j++) hreg[j] = 0.f;
    const float inv3 = 1.f / 3.f;

    for (int r = 0; r < NREL; r++) {
        __syncthreads();  // A_s / D_s consumers of previous iter done
        // stage mean-agg tile (fp16)
        {
            const float* aggr = g_agg + (size_t)r * NN * C;
            const float* cntr = g_cnt + r * NN;
            for (int it = tid; it < 128 * 32; it += 256) {
                int row = it >> 5, c4 = it & 31;
                int node = node0 + row;
                float4 v = make_float4(0.f, 0.f, 0.f, 0.f);
                if (node < NN) {
                    float inv = 1.f / fmaxf(cntr[node], 1.f);
                    float4 a = *reinterpret_cast<const float4*>(
                        aggr + (size_t)node * C + c4 * 4);
                    v.x = a.x * inv; v.y = a.y * inv;
                    v.z = a.z * inv; v.w = a.w * inv;
                }
                __half2* d = reinterpret_cast<__half2*>(A_s + row * HLD + c4 * 4);
                d[0] = __floats2half2_rn(v.x, v.y);
                d[1] = __floats2half2_rn(v.z, v.w);
            }
        }

        wmma::fragment<wmma::accumulator, 16, 16, 16, float> acc[4][2];
#pragma unroll
        for (int i = 0; i < 4; i++)
#pragma unroll
            for (int j = 0; j < 2; j++) wmma::fill_fragment(acc[i][j], 0.f);

        for (int kh = 0; kh < 2; kh++) {
            __syncthreads();  // W consumers done / A_s staged
            // stage k-half of Wl[r], Wr[r] (64 k rows x 128 n cols, fp16)
            for (int it = tid; it < 64 * 32; it += 256) {
                int kk = it >> 5, c4 = it & 31;
                size_t off = (size_t)r * C * C + (size_t)(kh * 64 + kk) * C + c4 * 4;
                float4 vl = *reinterpret_cast<const float4*>(Wl + off);
                float4 vr = *reinterpret_cast<const float4*>(Wr + off);
                __half2* dl = reinterpret_cast<__half2*>(Wl_s + kk * HLD + c4 * 4);
                dl[0] = __floats2half2_rn(vl.x, vl.y);
                dl[1] = __floats2half2_rn(vl.z, vl.w);
                __half2* dr = reinterpret_cast<__half2*>(Wr_s + kk * HLD + c4 * 4);
                dr[0] = __floats2half2_rn(vr.x, vr.y);
                dr[1] = __floats2half2_rn(vr.z, vr.w);
            }
            __syncthreads();

#pragma unroll
            for (int ks = 0; ks < 4; ks++) {
                int kloc = ks * 16;             // W row (local)
                int kglb = kh * 64 + kloc;      // A/X col
                wmma::fragment<wmma::matrix_a, 16, 16, 16, __half,
                               wmma::row_major> af[4], xf[4];
                wmma::fragment<wmma::matrix_b, 16, 16, 16, __half,
                               wmma::row_major> lf[2], rf[2];
#pragma unroll
                for (int i = 0; i < 4; i++) {
                    wmma::load_matrix_sync(af[i], A_s + (wm + i * 16) * HLD + kglb, HLD);
                    wmma::load_matrix_sync(xf[i], X_s + (wm + i * 16) * HLD + kglb, HLD);
                }
#pragma unroll
                for (int j = 0; j < 2; j++) {
                    wmma::load_matrix_sync(lf[j], Wl_s + kloc * HLD + wn + j * 16, HLD);
                    wmma::load_matrix_sync(rf[j], Wr_s + kloc * HLD + wn + j * 16, HLD);
                }
#pragma unroll
                for (int i = 0; i < 4; i++)
#pragma unroll
                    for (int j = 0; j < 2; j++) {
                        wmma::mma_sync(acc[i][j], af[i], lf[j], acc[i][j]);
                        wmma::mma_sync(acc[i][j], xf[i], rf[j], acc[i][j]);
                    }
            }
        }

        // dump D_r into D_s (f32 scratch; disjoint per warp), then epilogue
#pragma unroll
        for (int i = 0; i < 4; i++)
#pragma unroll
            for (int j = 0; j < 2; j++)
                wmma::store_matrix_sync(D_s + (wm + i * 16) * FLD + wn + j * 16,
                                        acc[i][j], FLD, wmma::mem_row_major);
        __syncthreads();

#pragma unroll
        for (int q = 0; q < 16; q++) {
            int c = ec0 + q * 4;
            float4 d = *reinterpret_cast<const float4*>(D_s + erow * FLD + c);
            float4 b = *reinterpret_cast<const float4*>(bls + r * C + c);
            hreg[q * 4 + 0] += fmaxf(d.x + b.x, 0.f) * inv3;
            hreg[q * 4 + 1] += fmaxf(d.y + b.y, 0.f) * inv3;
            hreg[q * 4 + 2] += fmaxf(d.z + b.z, 0.f) * inv3;
            hreg[q * 4 + 3] += fmaxf(d.w + b.w, 0.f) * inv3;
        }
    }

    // ---------------- second GEMM: D_f = h @ [Wlf | Wrf] --------------------
    __syncthreads();  // MMA readers of A_s / W done
    // write h (fp16) into A_s
#pragma unroll
    for (int q = 0; q < 16; q++) {
        int c = ec0 + q * 4;
        __half2* d = reinterpret_cast<__half2*>(A_s + erow * HLD + c);
        d[0] = __floats2half2_rn(hreg[q * 4 + 0], hreg[q * 4 + 1]);
        d[1] = __floats2half2_rn(hreg[q * 4 + 2], hreg[q * 4 + 3]);
    }
    // stage Wf = [Wlf | Wrf]: k rows 0..63 -> Wl_s, 64..127 -> Wr_s
    for (int it = tid; it < 128 * 32; it += 256) {
        int k = it >> 5, c4 = it & 31;
        int col = c4 * 4;
        float4 v;
        if (col < OC)
            v = *reinterpret_cast<const float4*>(Wlf + (size_t)k * OC + col);
        else
            v = *reinterpret_cast<const float4*>(Wrf + (size_t)k * OC + (col - OC));
        __half* base = (k < 64) ? (Wl_s + k * HLD) : (Wr_s + (k - 64) * HLD);
        __half2* d = reinterpret_cast<__half2*>(base + col);
        d[0] = __floats2half2_rn(v.x, v.y);
        d[1] = __floats2half2_rn(v.z, v.w);
    }
    __syncthreads();

    {
        wmma::fragment<wmma::accumulator, 16, 16, 16, float> acc2[4][2];
#pragma unroll
        for (int i = 0; i < 4; i++)
#pragma unroll
            for (int j = 0; j < 2; j++) wmma::fill_fragment(acc2[i][j], 0.f);

#pragma unroll
        for (int ks = 0; ks < 8; ks++) {
            int k = ks * 16;
            const __half* wbase = (k < 64) ? (Wl_s + k * HLD)
                                           : (Wr_s + (k - 64) * HLD);
            wmma::fragment<wmma::matrix_a, 16, 16, 16, __half,
                           wmma::row_major> hf[4];
            wmma::fragment<wmma::matrix_b, 16, 16, 16, __half,
                           wmma::row_major> wf[2];
#pragma unroll
            for (int i = 0; i < 4; i++)
                wmma::load_matrix_sync(hf[i], A_s + (wm + i * 16) * HLD + k, HLD);
#pragma unroll
            for (int j = 0; j < 2; j++)
                wmma::load_matrix_sync(wf[j], wbase + wn + j * 16, HLD);
#pragma unroll
            for (int i = 0; i < 4; i++)
#pragma unroll
                for (int j = 0; j < 2; j++)
                    wmma::mma_sync(acc2[i][j], hf[i], wf[j], acc2[i][j]);
        }

#pragma unroll
        for (int i = 0; i < 4; i++)
#pragma unroll
            for (int j = 0; j < 2; j++)
                wmma::store_matrix_sync(D_s + (wm + i * 16) * FLD + wn + j * 16,
                                        acc2[i][j], FLD, wmma::mem_row_major);
        __syncthreads();
    }

    // epilogue 2: t / po
    {
        int node = node0 + erow;
        if (node < NN) {
            if (ec0 == 0) {
                float* tp = g_t + (size_t)node * OC;
#pragma unroll
                for (int q = 0; q < 16; q++)
                    *reinterpret_cast<float4*>(tp + q * 4) =
                        *reinterpret_cast<const float4*>(D_s + erow * FLD + q * 4);
            } else {
                float* pp = g_po + (size_t)node * OC;
#pragma unroll
                for (int q = 0; q < 16; q++) {
                    float4 d = *reinterpret_cast<const float4*>(
                        D_s + erow * FLD + 64 + q * 4);
                    float4 b = *reinterpret_cast<const float4*>(blfs + q * 4);
                    *reinterpret_cast<float4*>(pp + q * 4) = make_float4(
                        d.x + b.x, d.y + b.y, d.z + b.z, d.w + b.w);
                }
            }
        }
    }
}

// ---------------- kernel 4: scatter t[src] into aggF[dst] (ei0) -------------
__global__ void k_scatter_t(const int* __restrict__ ei) {
    int hw = (blockIdx.x * blockDim.x + threadIdx.x) >> 4;
    int lane = threadIdx.x & 15;
    if (hw >= NE) return;
    int src = ei[hw];
    int dst = ei[NE + hw];
    if ((unsigned)src >= NN || (unsigned)dst >= NN) return;
    float4 v = *reinterpret_cast<const float4*>(g_t + (size_t)src * OC + lane * 4);
    red_add_v4(g_aggF + (size_t)dst * OC + lane * 4, v);
}

// ---------------- kernel 5: out = aggF / max(cnt0,1) + po -------------------
__global__ void k_final(float* __restrict__ out) {
    int i = blockIdx.x * blockDim.x + threadIdx.x;
    int stride = gridDim.x * blockDim.x;
    int n4 = NN * OC / 4;
    const float4* a4 = reinterpret_cast<const float4*>(g_aggF);
    const float4* p4 = reinterpret_cast<const float4*>(g_po);
    float4* o4 = reinterpret_cast<float4*>(out);
    for (int j = i; j < n4; j += stride) {
        int node = j / (OC / 4);
        float inv = 1.f / fmaxf(g_cnt[node], 1.f);
        float4 a = a4[j];
        float4 p = p4[j];
        o4[j] = make_float4(a.x * inv + p.x, a.y * inv + p.y,
                            a.z * inv + p.z, a.w * inv + p.w);
    }
}

// ---------------- launch ----------------------------------------------------
extern "C" void kernel_launch(void* const* d_in, const int* in_sizes, int n_in,
                              void* d_out, int out_size) {
    const float* x   = (const float*)d_in[0];
    const float* Wl  = (const float*)d_in[1];
    const float* bl  = (const float*)d_in[2];
    const float* Wr  = (const float*)d_in[3];
    const float* Wlf = (const float*)d_in[4];
    const float* blf = (const float*)d_in[5];
    const float* Wrf = (const float*)d_in[6];
    const int* ei0   = (const int*)d_in[7];
    const int* ei1   = (const int*)d_in[8];
    const int* ei2   = (const int*)d_in[9];
    float* out = (float*)d_out;

    // zero accumulators via memset nodes (copy engine path)
    void *pagg, *pcnt, *paggF;
    cudaGetSymbolAddress(&pagg, g_agg);
    cudaGetSymbolAddress(&pcnt, g_cnt);
    cudaGetSymbolAddress(&paggF, g_aggF);
    cudaMemsetAsync(pagg, 0, (size_t)NREL * NN * C * sizeof(float), 0);
    cudaMemsetAsync(pcnt, 0, (size_t)NREL * NN * sizeof(float), 0);
    cudaMemsetAsync(paggF, 0, (size_t)NN * OC * sizeof(float), 0);

    // 3-relation scatter in one launch
    dim3 sgrid((NE * 32 + 255) / 256, 3);
    k_scatter_x<<<sgrid, 256>>>(x, ei0, ei1, ei2);

    const int SMEMF = 2048 + (2 * 128 + 2 * 64) * HLD * 2 + 128 * FLD * 4;
    cudaFuncSetAttribute(k_gemm_fused, cudaFuncAttributeMaxDynamicSharedMemorySize, SMEMF);
    int gb = (NN + 127) / 128;  // 782
    k_gemm_fused<<<gb, 256, SMEMF>>>(x, Wl, bl, Wr, Wlf, blf, Wrf);

    int sb2 = (NE * 16 + 255) / 256;
    k_scatter_t<<<sb2, 256>>>(ei0);
    k_final<<<2048, 256>>>(out);
}

// round 6
// speedup vs baseline: 2.4118x; 1.2900x over previous
#include <cuda_runtime.h>
#include <cuda_fp16.h>
#include <mma.h>
#include <cstdint>

using namespace nvcuda;

#define NN 100000
#define NE 600000
#define C 128
#define OC 64
#define NREL 3
#define HLD 136   // fp16 tile stride (halves)
#define FLD 132   // f32 tile stride (floats)

// ---------------- scratch (static device globals) ---------------------------
__device__ float g_agg[(size_t)NREL * NN * C];
__device__ float g_cnt[NREL * NN];
__device__ float g_t[(size_t)NN * OC];
__device__ float g_aggF[(size_t)NN * OC];
__device__ float g_po[(size_t)NN * OC];
__device__ float g_bias_rep[NREL * 16 * C];   // bl replicated over 16 rows
__device__ float g_bias_rep_f[16 * C];        // [0|blf] replicated over 16 rows

__device__ __forceinline__ void red_add_v4(float* p, float4 v) {
    asm volatile("red.global.add.v4.f32 [%0], {%1, %2, %3, %4};"
                 :: "l"(p), "f"(v.x), "f"(v.y), "f"(v.z), "f"(v.w) : "memory");
}

// ---------------- kernel P: replicate biases --------------------------------
__global__ void k_prep(const float* __restrict__ bl, const float* __restrict__ blf) {
    int tid = threadIdx.x;
    for (int i = tid; i < NREL * 16 * C; i += 256) {
        int r = i / (16 * C);
        int col = i & (C - 1);
        g_bias_rep[i] = bl[r * C + col];
    }
    for (int i = tid; i < 16 * C; i += 256) {
        int col = i & (C - 1);
        g_bias_rep_f[i] = (col < OC) ? 0.f : blf[col - OC];
    }
}

// ---------------- kernel 1: scatter x, 4 edges per warp ---------------------
__global__ void k_scatter_x(const float* __restrict__ x,
                            const int* __restrict__ ei0,
                            const int* __restrict__ ei1,
                            const int* __restrict__ ei2) {
    int r = blockIdx.y;
    const int* ei = (r == 0) ? ei0 : (r == 1) ? ei1 : ei2;
    int w = (blockIdx.x * blockDim.x + threadIdx.x) >> 5;
    int lane = threadIdx.x & 31;
    int e0 = w * 4;
    if (e0 >= NE) return;
    int s[4], d[4];
    bool ok[4];
#pragma unroll
    for (int e = 0; e < 4; e++) {
        s[e] = ei[e0 + e];
        d[e] = ei[NE + e0 + e];
        ok[e] = ((unsigned)s[e] < NN) && ((unsigned)d[e] < NN);
    }
    float4 v[4];
#pragma unroll
    for (int e = 0; e < 4; e++)
        if (ok[e])
            v[e] = *reinterpret_cast<const float4*>(x + (size_t)s[e] * C + lane * 4);
#pragma unroll
    for (int e = 0; e < 4; e++)
        if (ok[e])
            red_add_v4(g_agg + (size_t)r * NN * C + (size_t)d[e] * C + lane * 4, v[e]);
    if (lane < 4 && ok[lane])
        atomicAdd(&g_cnt[r * NN + d[lane]], 1.f);
}

// ---------------- fused fp16 WMMA GEMM kernel (512 thr, 16 warps 4x4) -------
__global__ __launch_bounds__(512, 1)
void k_gemm_fused(const float* __restrict__ x,  const float* __restrict__ Wl,
                  const float* __restrict__ Wr, const float* __restrict__ Wlf,
                  const float* __restrict__ Wrf) {
    extern __shared__ char smraw[];
    // phase-1 layout
    __half* X_s  = reinterpret_cast<__half*>(smraw);             // [128][HLD]
    __half* A_s  = X_s + 128 * HLD;                              // [128][HLD]
    __half* Wl_s = A_s + 128 * HLD;                              // [64][HLD]
    __half* Wr_s = Wl_s + 64 * HLD;                              // [64][HLD]
    // phase-2 aliases
    float*  H32  = reinterpret_cast<float*>(smraw);              // [128][FLD] over X+A
    __half* Hh   = Wl_s;                                         // [128][HLD] over Wl+Wr
    __half* Wf_s = reinterpret_cast<__half*>(smraw);             // [128][HLD] over X
    float*  Df   = reinterpret_cast<float*>(smraw + 128 * HLD * 2); // [128][FLD] at A_s

    int tid  = threadIdx.x;
    int wid  = tid >> 5;
    int node0 = blockIdx.x * 128;
    int wm = (wid >> 2) * 32;   // warp row offset (4 row-groups)
    int wn = (wid & 3) * 32;    // warp col offset (4 col-groups)

    // stage X tile (fp16)
    for (int it = tid; it < 128 * 32; it += 512) {
        int row = it >> 5, c4 = it & 31;
        int node = node0 + row;
        float4 v = make_float4(0.f, 0.f, 0.f, 0.f);
        if (node < NN)
            v = *reinterpret_cast<const float4*>(x + (size_t)node * C + c4 * 4);
        __half2* dp = reinterpret_cast<__half2*>(X_s + row * HLD + c4 * 4);
        dp[0] = __floats2half2_rn(v.x, v.y);
        dp[1] = __floats2half2_rn(v.z, v.w);
    }

    wmma::fragment<wmma::accumulator, 16, 16, 16, float> hfrag[2][2];
#pragma unroll
    for (int i = 0; i < 2; i++)
#pragma unroll
        for (int j = 0; j < 2; j++) wmma::fill_fragment(hfrag[i][j], 0.f);
    const float inv3 = 1.f / 3.f;

    for (int r = 0; r < NREL; r++) {
        __syncthreads();  // prior MMAs done reading A_s (and X staged, iter 0)
        // stage mean-agg tile (fp16)
        {
            const float* aggr = g_agg + (size_t)r * NN * C;
            const float* cntr = g_cnt + r * NN;
            for (int it = tid; it < 128 * 32; it += 512) {
                int row = it >> 5, c4 = it & 31;
                int node = node0 + row;
                float4 v = make_float4(0.f, 0.f, 0.f, 0.f);
                if (node < NN) {
                    float inv = 1.f / fmaxf(cntr[node], 1.f);
                    float4 a = *reinterpret_cast<const float4*>(
                        aggr + (size_t)node * C + c4 * 4);
                    v.x = a.x * inv; v.y = a.y * inv;
                    v.z = a.z * inv; v.w = a.w * inv;
                }
                __half2* dp = reinterpret_cast<__half2*>(A_s + row * HLD + c4 * 4);
                dp[0] = __floats2half2_rn(v.x, v.y);
                dp[1] = __floats2half2_rn(v.z, v.w);
            }
        }

        // acc = bias (fragment load from replicated global bias tile)
        wmma::fragment<wmma::accumulator, 16, 16, 16, float> acc[2][2];
#pragma unroll
        for (int i = 0; i < 2; i++)
#pragma unroll
            for (int j = 0; j < 2; j++)
                wmma::load_matrix_sync(acc[i][j],
                    g_bias_rep + r * 16 * C + wn + j * 16, C, wmma::mem_row_major);

        for (int kh = 0; kh < 2; kh++) {
            __syncthreads();  // A_s staged / prior W readers done
            for (int it = tid; it < 64 * 32; it += 512) {
                int kk = it >> 5, c4 = it & 31;
                size_t off = (size_t)r * C * C + (size_t)(kh * 64 + kk) * C + c4 * 4;
                float4 vl = *reinterpret_cast<const float4*>(Wl + off);
                float4 vr = *reinterpret_cast<const float4*>(Wr + off);
                __half2* dl = reinterpret_cast<__half2*>(Wl_s + kk * HLD + c4 * 4);
                dl[0] = __floats2half2_rn(vl.x, vl.y);
                dl[1] = __floats2half2_rn(vl.z, vl.w);
                __half2* dr = reinterpret_cast<__half2*>(Wr_s + kk * HLD + c4 * 4);
                dr[0] = __floats2half2_rn(vr.x, vr.y);
                dr[1] = __floats2half2_rn(vr.z, vr.w);
            }
            __syncthreads();

#pragma unroll
            for (int ks = 0; ks < 4; ks++) {
                int kloc = ks * 16;
                int kglb = kh * 64 + kloc;
                wmma::fragment<wmma::matrix_a, 16, 16, 16, __half,
                               wmma::row_major> af[2], xf[2];
                wmma::fragment<wmma::matrix_b, 16, 16, 16, __half,
                               wmma::row_major> lf[2], rf[2];
#pragma unroll
                for (int i = 0; i < 2; i++) {
                    wmma::load_matrix_sync(af[i], A_s + (wm + i * 16) * HLD + kglb, HLD);
                    wmma::load_matrix_sync(xf[i], X_s + (wm + i * 16) * HLD + kglb, HLD);
                }
#pragma unroll
                for (int j = 0; j < 2; j++) {
                    wmma::load_matrix_sync(lf[j], Wl_s + kloc * HLD + wn + j * 16, HLD);
                    wmma::load_matrix_sync(rf[j], Wr_s + kloc * HLD + wn + j * 16, HLD);
                }
#pragma unroll
                for (int i = 0; i < 2; i++)
#pragma unroll
                    for (int j = 0; j < 2; j++) {
                        wmma::mma_sync(acc[i][j], af[i], lf[j], acc[i][j]);
                        wmma::mma_sync(acc[i][j], xf[i], rf[j], acc[i][j]);
                    }
            }
        }

        // h += relu(acc)/3  (elementwise on identical fragment layouts)
#pragma unroll
        for (int i = 0; i < 2; i++)
#pragma unroll
            for (int j = 0; j < 2; j++)
#pragma unroll
                for (int t = 0; t < hfrag[i][j].num_elements; t++)
                    hfrag[i][j].x[t] += fmaxf(acc[i][j].x[t], 0.f) * inv3;
    }

    // ---------------- final GEMM: D_f = h @ [Wlf | Wrf] ---------------------
    __syncthreads();  // last MMAs done reading X_s/A_s/W
    // store h (f32) into H32 (aliases X_s+A_s)
#pragma unroll
    for (int i = 0; i < 2; i++)
#pragma unroll
        for (int j = 0; j < 2; j++)
            wmma::store_matrix_sync(H32 + (wm + i * 16) * FLD + wn + j * 16,
                                    hfrag[i][j], FLD, wmma::mem_row_major);
    __syncthreads();
    // convert H32 -> Hh (fp16, aliases Wl_s+Wr_s)
    for (int it = tid; it < 128 * 64; it += 512) {
        int row = it >> 6, c2 = it & 63;
        float2 v = *reinterpret_cast<const float2*>(H32 + row * FLD + c2 * 2);
        *reinterpret_cast<__half2*>(Hh + row * HLD + c2 * 2) =
            __floats2half2_rn(v.x, v.y);
    }
    __syncthreads();
    // stage Wf = [Wlf | Wrf] (fp16, aliases X_s; H32 fully consumed)
    for (int it = tid; it < 128 * 32; it += 512) {
        int k = it >> 5, c4 = it & 31;
        int col = c4 * 4;
        float4 v;
        if (col < OC)
            v = *reinterpret_cast<const float4*>(Wlf + (size_t)k * OC + col);
        else
            v = *reinterpret_cast<const float4*>(Wrf + (size_t)k * OC + (col - OC));
        __half2* dp = reinterpret_cast<__half2*>(Wf_s + k * HLD + col);
        dp[0] = __floats2half2_rn(v.x, v.y);
        dp[1] = __floats2half2_rn(v.z, v.w);
    }
    __syncthreads();

    {
        wmma::fragment<wmma::accumulator, 16, 16, 16, float> acc2[2][2];
#pragma unroll
        for (int i = 0; i < 2; i++)
#pragma unroll
            for (int j = 0; j < 2; j++)
                wmma::load_matrix_sync(acc2[i][j],
                    g_bias_rep_f + wn + j * 16, C, wmma::mem_row_major);

#pragma unroll
        for (int ks = 0; ks < 8; ks++) {
            int k = ks * 16;
            wmma::fragment<wmma::matrix_a, 16, 16, 16, __half,
                           wmma::row_major> hf[2];
            wmma::fragment<wmma::matrix_b, 16, 16, 16, __half,
                           wmma::row_major> wf[2];
#pragma unroll
            for (int i = 0; i < 2; i++)
                wmma::load_matrix_sync(hf[i], Hh + (wm + i * 16) * HLD + k, HLD);
#pragma unroll
            for (int j = 0; j < 2; j++)
                wmma::load_matrix_sync(wf[j], Wf_s + k * HLD + wn + j * 16, HLD);
#pragma unroll
            for (int i = 0; i < 2; i++)
#pragma unroll
                for (int j = 0; j < 2; j++)
                    wmma::mma_sync(acc2[i][j], hf[i], wf[j], acc2[i][j]);
        }
        __syncthreads();  // all warps done reading Hh/Wf
#pragma unroll
        for (int i = 0; i < 2; i++)
#pragma unroll
            for (int j = 0; j < 2; j++)
                wmma::store_matrix_sync(Df + (wm + i * 16) * FLD + wn + j * 16,
                                        acc2[i][j], FLD, wmma::mem_row_major);
        __syncthreads();
    }

    // epilogue: t (cols 0..63), po (cols 64..127, bias already in acc2)
    {
        int row = tid >> 2;
        int ec  = (tid & 3) * 32;
        int node = node0 + row;
        if (node < NN) {
            if (ec < OC) {
                float* tp = g_t + (size_t)node * OC + ec;
#pragma unroll
                for (int q = 0; q < 8; q++)
                    *reinterpret_cast<float4*>(tp + q * 4) =
                        *reinterpret_cast<const float4*>(Df + row * FLD + ec + q * 4);
            } else {
                float* pp = g_po + (size_t)node * OC + (ec - OC);
#pragma unroll
                for (int q = 0; q < 8; q++)
                    *reinterpret_cast<float4*>(pp + q * 4) =
                        *reinterpret_cast<const float4*>(Df + row * FLD + ec + q * 4);
            }
        }
    }
}

// ---------------- kernel 4: scatter t, 4 edges per half-warp ----------------
__global__ void k_scatter_t(const int* __restrict__ ei) {
    int hw = (blockIdx.x * blockDim.x + threadIdx.x) >> 4;
    int lane = threadIdx.x & 15;
    int e0 = hw * 4;
    if (e0 >= NE) return;
    int s[4], d[4];
    bool ok[4];
#pragma unroll
    for (int e = 0; e < 4; e++) {
        s[e] = ei[e0 + e];
        d[e] = ei[NE + e0 + e];
        ok[e] = ((unsigned)s[e] < NN) && ((unsigned)d[e] < NN);
    }
    float4 v[4];
#pragma unroll
    for (int e = 0; e < 4; e++)
        if (ok[e])
            v[e] = *reinterpret_cast<const float4*>(g_t + (size_t)s[e] * OC + lane * 4);
#pragma unroll
    for (int e = 0; e < 4; e++)
        if (ok[e])
            red_add_v4(g_aggF + (size_t)d[e] * OC + lane * 4, v[e]);
}

// ---------------- kernel 5: out = aggF / max(cnt0,1) + po -------------------
__global__ void k_final(float* __restrict__ out) {
    int i = blockIdx.x * blockDim.x + threadIdx.x;
    int stride = gridDim.x * blockDim.x;
    int n4 = NN * OC / 4;
    const float4* a4 = reinterpret_cast<const float4*>(g_aggF);
    const float4* p4 = reinterpret_cast<const float4*>(g_po);
    float4* o4 = reinterpret_cast<float4*>(out);
    for (int j = i; j < n4; j += stride) {
        int node = j / (OC / 4);
        float inv = 1.f / fmaxf(g_cnt[node], 1.f);
        float4 a = a4[j];
        float4 p = p4[j];
        o4[j] = make_float4(a.x * inv + p.x, a.y * inv + p.y,
                            a.z * inv + p.z, a.w * inv + p.w);
    }
}

// ---------------- launch ----------------------------------------------------
extern "C" void kernel_launch(void* const* d_in, const int* in_sizes, int n_in,
                              void* d_out, int out_size) {
    const float* x   = (const float*)d_in[0];
    const float* Wl  = (const float*)d_in[1];
    const float* bl  = (const float*)d_in[2];
    const float* Wr  = (const float*)d_in[3];
    const float* Wlf = (const float*)d_in[4];
    const float* blf = (const float*)d_in[5];
    const float* Wrf = (const float*)d_in[6];
    const int* ei0   = (const int*)d_in[7];
    const int* ei1   = (const int*)d_in[8];
    const int* ei2   = (const int*)d_in[9];
    float* out = (float*)d_out;

    void *pagg, *pcnt, *paggF;
    cudaGetSymbolAddress(&pagg, g_agg);
    cudaGetSymbolAddress(&pcnt, g_cnt);
    cudaGetSymbolAddress(&paggF, g_aggF);
    cudaMemsetAsync(pagg, 0, (size_t)NREL * NN * C * sizeof(float), 0);
    cudaMemsetAsync(pcnt, 0, (size_t)NREL * NN * sizeof(float), 0);
    cudaMemsetAsync(paggF, 0, (size_t)NN * OC * sizeof(float), 0);

    k_prep<<<1, 256>>>(bl, blf);

    // 4 edges per warp, 8 warps per block -> 18750 blocks, y = relation
    dim3 sgrid((NE / 4 + 7) / 8, 3);
    k_scatter_x<<<sgrid, 256>>>(x, ei0, ei1, ei2);

    const int SMEMF = (2 * 128 + 2 * 64) * HLD * 2;  // 104448
    cudaFuncSetAttribute(k_gemm_fused, cudaFuncAttributeMaxDynamicSharedMemorySize, SMEMF);
    int gb = (NN + 127) / 128;  // 782
    k_gemm_fused<<<gb, 512, SMEMF>>>(x, Wl, Wr, Wlf, Wrf);

    // 4 edges per half-warp, 16 half-warps per block -> 9375 blocks
    k_scatter_t<<<(NE / 4 + 15) / 16, 256>>>(ei0);
    k_final<<<2048, 256>>>(out);
}